// round 14
// baseline (speedup 1.0000x reference)
#include <cuda_runtime.h>
#include <math.h>

#define H 512
#define B 32
#define T 32
#define V 6000
#define NS 6
#define HB (H*B)
#define NBLK 128
#define TBH (T*B*H)

typedef unsigned long long ull;

// ---------------- scratch layout (floats) ----------------
// Pair-transposed (PT) layout: float (b,k) at (k>>1)*64 + b*2 + (k&1)
#define OFF_CTXT 0
#define OFF_QT   (OFF_CTXT + HB)
#define OFF_DH0T (OFF_QT + HB)
#define OFF_DH1T (OFF_DH0T + 2*HB)
#define OFF_EH0T (OFF_DH1T + 2*HB)
#define OFF_EH1T (OFF_EH0T + 2*HB)
#define OFF_DC0  (OFF_EH1T + 2*HB)
#define OFF_DC1  (OFF_DC0 + HB)
#define OFF_EC0  (OFF_DC1 + HB)
#define OFF_EC1  (OFF_EC0 + HB)
#define ZERO_CNT (OFF_EC1 + HB)
#define OFF_XEMBD ZERO_CNT
#define OFF_XEMBE (OFF_XEMBD + 6*TBH)
#define OFF_G0D  (OFF_XEMBE + 5*TBH)
#define OFF_G0E  (OFF_G0D + 6*T*B*4*H)
#define OFF_DOUT (OFF_G0E + 5*T*B*4*H)   // 6 per-sentence slices
#define OFF_NORM (OFF_DOUT + 6*TBH)      // 5 slices
#define OFF_ERAW (OFF_NORM + 5*TBH)
#define OFF_EOUT (OFF_ERAW + TBH)
#define OFF_KPRE (OFF_EOUT + TBH)
#define OFF_PACK (OFF_KPRE + TBH)
#define PACK_SZ  (H*H*4)
#define N_PACK   7
#define BUF_TOTAL (OFF_PACK + (size_t)N_PACK*PACK_SZ)

__device__ __align__(256) float g_buf[BUF_TOTAL];
__device__ int   g_mask[(NS-1)*B*T];
__device__ unsigned g_gen;
__device__ unsigned g_arr[NBLK];

// ---------------- low-level helpers ----------------
#define FMA2(a,x,w) asm("fma.rn.f32x2 %0, %1, %2, %0;" : "+l"(a) : "l"(x), "l"(w))
__device__ __forceinline__ ull pk2(float lo, float hi) {
    ull r; asm("mov.b64 %0, {%1,%2};" : "=l"(r) : "f"(lo), "f"(hi)); return r;
}
__device__ __forceinline__ float2 up2(ull v) {
    float2 f; asm("mov.b64 {%0,%1}, %2;" : "=f"(f.x), "=f"(f.y) : "l"(v)); return f;
}
__device__ __forceinline__ float ldcgf(const float* p) {
    float v; asm volatile("ld.global.cg.f32 %0, [%1];" : "=f"(v) : "l"(p)); return v;
}
__device__ __forceinline__ ull ldcg64(const ull* p) {
    ull v; asm volatile("ld.global.cg.b64 %0, [%1];" : "=l"(v) : "l"(p)); return v;
}
__device__ __forceinline__ ulonglong2 ldcgv2(const ulonglong2* p) {
    ulonglong2 v;
    asm volatile("ld.global.cg.v2.u64 {%0,%1}, [%2];" : "=l"(v.x), "=l"(v.y) : "l"(p));
    return v;
}
__device__ __forceinline__ void st_rel(unsigned* p, unsigned v) {
    asm volatile("st.release.gpu.global.u32 [%0], %1;" :: "l"(p), "r"(v) : "memory");
}
__device__ __forceinline__ unsigned ld_acq(const unsigned* p) {
    unsigned v; asm volatile("ld.acquire.gpu.global.u32 %0, [%1];" : "=r"(v) : "l"(p) : "memory"); return v;
}

// ---------------- 2-hop grid barrier (monotonic generations; replay-safe) ----------------
__device__ __forceinline__ void gridbar(unsigned &mygen) {
    __syncthreads();
    mygen++;
    if (threadIdx.x == 0) st_rel(&g_arr[blockIdx.x], mygen);
    if (blockIdx.x == 0) {
        if (threadIdx.x < NBLK) {
            while ((int)(ld_acq(&g_arr[threadIdx.x]) - mygen) < 0) { }
        }
        __syncthreads();
        if (threadIdx.x == 0) st_rel(&g_gen, mygen);
    } else {
        if (threadIdx.x == 0) {
            // contested single-line poll: HW-sleep backoff to cut L2 pressure
            while ((int)(ld_acq(&g_gen) - mygen) < 0) { __nanosleep(32); }
        }
        __syncthreads();
    }
}

// ---------------- zero recurrent state ----------------
__global__ void k_zero() {
    int i = blockIdx.x * 256 + threadIdx.x;
    if (i < ZERO_CNT) g_buf[i] = 0.0f;
}

// ---------------- fused pack: all 7 weight slabs in one launch (blockIdx.z selects) ----------------
__global__ void k_packall(const float* __restrict__ dWih0, const float* __restrict__ dWih1,
                          const float* __restrict__ dWhh,  const float* __restrict__ eWih,
                          const float* __restrict__ eWhh) {
    int kp = blockIdx.x * 128 + threadIdx.x;
    int j  = blockIdx.y;
    int z  = blockIdx.z;
    const float* W; int ldw;
    switch (z) {
        case 0: W = dWih0 + H;       ldw = 2*H; break;  // P_DL0C (ctx cols)
        case 1: W = dWhh;            ldw = H;   break;  // P_DL0H
        case 2: W = dWih1;           ldw = H;   break;  // P_DL1X
        case 3: W = dWhh + 4*H*H;    ldw = H;   break;  // P_DL1H
        case 4: W = eWhh;            ldw = H;   break;  // P_EL0H
        case 5: W = eWih + 4*H*H;    ldw = H;   break;  // P_EL1X
        default:W = eWhh + 4*H*H;    ldw = H;   break;  // P_EL1H
    }
    float* P = g_buf + OFF_PACK + (size_t)z*PACK_SZ;
    float* o = P + ((size_t)j*256 + kp)*8;
    #pragma unroll
    for (int g = 0; g < 4; g++) {
        o[g*2+0] = W[(size_t)(g*H + j) * ldw + 2*kp];
        o[g*2+1] = W[(size_t)(g*H + j) * ldw + 2*kp + 1];
    }
}

// ---------------- batched embedding gather (all sentences) ----------------
__global__ void k_gather(const int* __restrict__ inputs, const int* __restrict__ targets,
                         const float* __restrict__ emb, float* __restrict__ X, int is_dec) {
    int row = blockIdx.x;          // s*1024 + t*32 + b
    int s = row >> 10, t = (row >> 5) & 31, b = row & 31;
    int tok;
    if (is_dec) {
        if (t == 0) tok = 1;
        else tok = (s == 0) ? inputs[b*192 + (t-1)] : targets[b*160 + (s-1)*32 + (t-1)];
    } else {
        tok = (s == 0) ? inputs[b*192 + t] : targets[b*160 + (s-1)*32 + t];
    }
    const float4* e = (const float4*)(emb + (size_t)tok * H);
    float4* o = (float4*)(X + (size_t)row * H);
    for (int i = threadIdx.x; i < H/4; i += 128) o[i] = e[i];
}

// ---------------- all masks upfront ----------------
__global__ void k_maskall(const int* __restrict__ inputs, const int* __restrict__ targets) {
    int b = threadIdx.x;
    if (b >= B) return;
    for (int s = 0; s < NS-1; s++) {
        int seen = 0;
        for (int t = 0; t < T; t++) {
            g_mask[s*B*T + b*T + t] = seen;
            int tok = (s == 0) ? inputs[b*192 + t] : targets[b*160 + (s-1)*32 + t];
            if (tok == 2 || tok == 3) seen = 1;
        }
    }
}

// ---------------- SGEMM 128x128, 8x8 micro, FFMA2, double-buffered ----------------
__global__ __launch_bounds__(256) void k_gemm2(
    const float* __restrict__ A,
    const float* __restrict__ W, int ldw,
    const float* __restrict__ bias,
    float* __restrict__ C, int N, int mode, int spar)
{
    __shared__ float As[2][16][136];
    __shared__ float Bs[2][16][136];
    int tid = threadIdx.x;
    int m0 = blockIdx.y*128, n0 = blockIdx.x*128;
    int lr = tid >> 1, lc = (tid & 1)*8;
    int ty = tid >> 4, tx = tid & 15;
    ull acc2[8][4];
    #pragma unroll
    for (int i = 0; i < 8; i++)
        #pragma unroll
        for (int jp = 0; jp < 4; jp++) acc2[i][jp] = 0ull;

    const float* Arow = A + (size_t)(m0 + lr) * 512;
    bool bvalid = (n0 + lr) < N;
    const float* Wrow = W + (size_t)(bvalid ? (n0 + lr) : 0) * ldw;
    float4 z4 = make_float4(0.f, 0.f, 0.f, 0.f);

    float4 pa0 = *(const float4*)(Arow + lc);
    float4 pa1 = *(const float4*)(Arow + lc + 4);
    float4 pb0 = bvalid ? *(const float4*)(Wrow + lc) : z4;
    float4 pb1 = bvalid ? *(const float4*)(Wrow + lc + 4) : z4;
    As[0][lc+0][lr]=pa0.x; As[0][lc+1][lr]=pa0.y; As[0][lc+2][lr]=pa0.z; As[0][lc+3][lr]=pa0.w;
    As[0][lc+4][lr]=pa1.x; As[0][lc+5][lr]=pa1.y; As[0][lc+6][lr]=pa1.z; As[0][lc+7][lr]=pa1.w;
    Bs[0][lc+0][lr]=pb0.x; Bs[0][lc+1][lr]=pb0.y; Bs[0][lc+2][lr]=pb0.z; Bs[0][lc+3][lr]=pb0.w;
    Bs[0][lc+4][lr]=pb1.x; Bs[0][lc+5][lr]=pb1.y; Bs[0][lc+6][lr]=pb1.z; Bs[0][lc+7][lr]=pb1.w;
    __syncthreads();

    int buf = 0;
    for (int k0 = 16; k0 <= 512; k0 += 16) {
        bool more = k0 < 512;
        if (more) {
            pa0 = *(const float4*)(Arow + k0 + lc);
            pa1 = *(const float4*)(Arow + k0 + lc + 4);
            pb0 = bvalid ? *(const float4*)(Wrow + k0 + lc) : z4;
            pb1 = bvalid ? *(const float4*)(Wrow + k0 + lc + 4) : z4;
        }
        #pragma unroll
        for (int k = 0; k < 16; k++) {
            float4 a0 = *(const float4*)&As[buf][k][ty*8];
            float4 a1 = *(const float4*)&As[buf][k][ty*8+4];
            ulonglong2 b0 = *(const ulonglong2*)&Bs[buf][k][tx*8];
            ulonglong2 b1 = *(const ulonglong2*)&Bs[buf][k][tx*8+4];
            float av[8] = {a0.x,a0.y,a0.z,a0.w,a1.x,a1.y,a1.z,a1.w};
            #pragma unroll
            for (int i = 0; i < 8; i++) {
                ull ad = pk2(av[i], av[i]);
                FMA2(acc2[i][0], ad, b0.x);
                FMA2(acc2[i][1], ad, b0.y);
                FMA2(acc2[i][2], ad, b1.x);
                FMA2(acc2[i][3], ad, b1.y);
            }
        }
        if (more) {
            int nb = buf ^ 1;
            As[nb][lc+0][lr]=pa0.x; As[nb][lc+1][lr]=pa0.y; As[nb][lc+2][lr]=pa0.z; As[nb][lc+3][lr]=pa0.w;
            As[nb][lc+4][lr]=pa1.x; As[nb][lc+5][lr]=pa1.y; As[nb][lc+6][lr]=pa1.z; As[nb][lc+7][lr]=pa1.w;
            Bs[nb][lc+0][lr]=pb0.x; Bs[nb][lc+1][lr]=pb0.y; Bs[nb][lc+2][lr]=pb0.z; Bs[nb][lc+3][lr]=pb0.w;
            Bs[nb][lc+4][lr]=pb1.x; Bs[nb][lc+5][lr]=pb1.y; Bs[nb][lc+6][lr]=pb1.z; Bs[nb][lc+7][lr]=pb1.w;
        }
        __syncthreads();
        buf ^= 1;
    }
    #pragma unroll
    for (int i = 0; i < 8; i++) {
        int m = m0 + ty*8 + i;
        #pragma unroll
        for (int jp = 0; jp < 4; jp++) {
            float2 p = up2(acc2[i][jp]);
            int n = n0 + tx*8 + jp*2;
            #pragma unroll
            for (int e = 0; e < 2; e++) {
                int ne = n + e;
                if (ne < N) {
                    float v = (e ? p.y : p.x) + bias[ne];
                    if (mode == 0) C[(size_t)m*N + ne] = v;
                    else {
                        int t = (m >> 5) & 31, b = m & 31;
                        C[(((size_t)b*5 + spar)*32 + t)*(size_t)V + ne] = v;
                    }
                }
            }
        }
    }
}

// ---------------- layernorm ----------------
__global__ void k_ln(const float* __restrict__ in, float* __restrict__ out,
                     const float* __restrict__ g, const float* __restrict__ bb) {
    int row = blockIdx.x, tid = threadIdx.x;
    const float* x = in + (size_t)row * H;
    float v[4], s = 0.f;
    #pragma unroll
    for (int i = 0; i < 4; i++) { v[i] = x[tid + i*128]; s += v[i]; }
    __shared__ float rs[4];
    for (int o = 16; o; o >>= 1) s += __shfl_xor_sync(0xffffffffu, s, o);
    int warp = tid >> 5, lane = tid & 31;
    if (lane == 0) rs[warp] = s;
    __syncthreads();
    float mean = (rs[0] + rs[1] + rs[2] + rs[3]) / (float)H;
    __syncthreads();
    float s2 = 0.f;
    #pragma unroll
    for (int i = 0; i < 4; i++) { float d = v[i] - mean; s2 += d*d; }
    for (int o = 16; o; o >>= 1) s2 += __shfl_xor_sync(0xffffffffu, s2, o);
    if (lane == 0) rs[warp] = s2;
    __syncthreads();
    float var = (rs[0] + rs[1] + rs[2] + rs[3]) / (float)H;
    float inv = rsqrtf(var + 1e-5f);
    #pragma unroll
    for (int i = 0; i < 4; i++) {
        int c = tid + i*128;
        out[(size_t)row*H + c] = (v[i] - mean) * inv * g[c] + bb[c];
    }
}

// ---------------- cooperative chunk staging (32 k-pairs x 2 grps) ----------------
// NOTE: block-cooperative — x0/x1 must be identical across ALL threads
// (x0 feeds chunk-half 0 = grp0's source; x1 feeds chunk-half 1 = grp1's source).
__device__ __forceinline__ void ld_chunk(const float* x0, const float* x1, int c, int tid,
                                         ulonglong2* r) {
    #pragma unroll
    for (int q = 0; q < 4; q++) {
        int idx = tid + q*256;
        const float* src = (idx >> 9) ? x1 : x0;
        int off = idx & 511;
        r[q] = ldcgv2((const ulonglong2*)src + (size_t)c*512 + off);
    }
}
__device__ __forceinline__ void st_chunk(ull* Xs, int b, int tid, const ulonglong2* r) {
    ulonglong2* dst = (ulonglong2*)(Xs + (size_t)b*2048);
    #pragma unroll
    for (int q = 0; q < 4; q++) dst[tid + q*256] = r[q];
}

// ---------------- fused LSTM phase: smem-staged x, smem weights, f32x2 ----------------
__device__ __forceinline__ void lstm_phase2(
    const ulonglong2* wv, int nkp,
    const float* x0, const float* x1, ull* Xs,
    const float* base, int base_vec,
    ull (*Red)[4][32],
    int tid, int jj, int grp, int lane, int j,
    float* cst, float* hT, float* extraBase, int extraStride)
{
    ull ai, af, ag, ao;
    float cold = 0.f;
    if (grp == 0) {
        cold = ldcgf(cst + (size_t)lane*H + j);
        float bi, bf, bg, bo;
        if (base_vec) { bi = base[j]; bf = base[H+j]; bg = base[2*H+j]; bo = base[3*H+j]; }
        else {
            const float* r = base + (size_t)lane * (4*H);
            bi = r[j]; bf = r[H+j]; bg = r[2*H+j]; bo = r[3*H+j];
        }
        ai = pk2(bi, 0.f); af = pk2(bf, 0.f); ag = pk2(bg, 0.f); ao = pk2(bo, 0.f);
    } else { ai = af = ag = ao = 0ull; }

    int nc = nkp >> 5;
    ulonglong2 r[4];
    ld_chunk(x0, x1, 0, tid, r);
    st_chunk(Xs, 0, tid, r);
    __syncthreads();
    for (int c = 0; c < nc; c++) {
        if (c + 1 < nc) ld_chunk(x0, x1, c+1, tid, r);
        const ull* xb = Xs + (size_t)(c & 1)*2048 + grp*1024 + lane;
        const ulonglong2* wc = wv + (size_t)c*64;
        #pragma unroll
        for (int kp = 0; kp < 32; kp++) {
            ull x2 = xb[kp*32];
            ulonglong2 wa = wc[kp*2];
            ulonglong2 wb = wc[kp*2 + 1];
            FMA2(ai, x2, wa.x); FMA2(af, x2, wa.y);
            FMA2(ag, x2, wb.x); FMA2(ao, x2, wb.y);
        }
        if (c + 1 < nc) st_chunk(Xs, (c+1) & 1, tid, r);
        __syncthreads();
    }
    if (grp == 1) {
        Red[jj][0][lane] = ai; Red[jj][1][lane] = af;
        Red[jj][2][lane] = ag; Red[jj][3][lane] = ao;
    }
    __syncthreads();
    if (grp == 0) {
        float2 A, R;
        A = up2(ai); R = up2(Red[jj][0][lane]); float gi = A.x + A.y + R.x + R.y;
        A = up2(af); R = up2(Red[jj][1][lane]); float gf = A.x + A.y + R.x + R.y;
        A = up2(ag); R = up2(Red[jj][2][lane]); float gg = A.x + A.y + R.x + R.y;
        A = up2(ao); R = up2(Red[jj][3][lane]); float go = A.x + A.y + R.x + R.y;
        float si = 1.f / (1.f + expf(-gi));
        float sf = 1.f / (1.f + expf(-gf));
        float so = 1.f / (1.f + expf(-go));
        float c2 = sf * cold + si * tanhf(gg);
        float h2 = so * tanhf(c2);
        cst[(size_t)lane*H + j] = c2;
        hT[((j>>1)*64) + lane*2 + (j&1)] = h2;
        if (extraBase) extraBase[(size_t)lane*extraStride + j] = h2;
    }
}

// ---------------- persistent decoder kernel ----------------
#define DEC_QW_OFF  131072
#define DEC_QS_OFF  (DEC_QW_OFF + 8192)
#define DEC_SC_OFF  (DEC_QS_OFF + 2048)
#define DEC_RED_OFF (DEC_SC_OFF + 128)
#define DEC_XS_OFF  (DEC_RED_OFF + 4096)
#define SMEM_DEC    (DEC_XS_OFF + 32768)
__global__ __launch_bounds__(256, 1) void k_dec(
    const float* __restrict__ G0, const float* __restrict__ biasL1,
    const float* __restrict__ PC, const float* __restrict__ PH0,
    const float* __restrict__ PX1, const float* __restrict__ PH1,
    float* ctxT, float* h0T, float* h1T, float* c0, float* c1,
    float* qT, const float* __restrict__ attW, const float* __restrict__ attv,
    const float* __restrict__ Kpre, const float* __restrict__ Eout,
    const int* __restrict__ mask,
    float* Dout, int has_attn)
{
    extern __shared__ char smem[];
    float4* W4 = (float4*)smem;
    ull*  Qw  = (ull*)(smem + DEC_QW_OFF);
    float* qs = (float*)(smem + DEC_QS_OFF);
    float* sc = (float*)(smem + DEC_SC_OFF);
    ull (*Red)[4][32] = (ull (*)[4][32])(smem + DEC_RED_OFF);
    ull*  Xs  = (ull*)(smem + DEC_XS_OFF);

    int tid = threadIdx.x, warp = tid >> 5, lane = tid & 31;
    int jj = warp & 3, grp = warp >> 2;
    int bid = blockIdx.x;
    int jb = bid*4, j = jb + jj;
    unsigned mygen = ld_acq(&g_gen);

    // weights: layer0 = [PC | PH0], layer1 = [PX1 | PH1]; linear 32KB slab copies
    {
        const float* srcs[4] = { PC, PH0, PX1, PH1 };
        for (int m = 0; m < 4; m++) {
            const float4* s4 = ((const float4*)srcs[m]) + (size_t)bid*2048;
            float4* d4 = W4 + (size_t)m*2048;
            for (int i = tid; i < 2048; i += 256) d4[i] = s4[i];
        }
        for (int i = tid; i < 1024; i += 256) {
            int kp = i >> 2, jl = i & 3;
            Qw[i] = *(const ull*)(attW + (size_t)(jb + jl)*1024 + kp*2);
        }
    }
    __syncthreads();
    // weight views: has_attn -> L0 = [PC|PH0] grp-slab; else L0 = PH0 only, grp splits kp
    const ulonglong2* wv0g = has_attn
        ? (const ulonglong2*)(W4 + (size_t)grp*2048 + (size_t)jj*512)
        : (const ulonglong2*)(W4 + 2048 + (size_t)jj*512 + (size_t)grp*256);
    const ulonglong2* wv1g = (const ulonglong2*)(W4 + 4096 + (size_t)grp*2048 + (size_t)jj*512);
    const ull* qwu = Qw;

    for (int t = 0; t < T; t++) {
        int p = t & 1;
        float* h0r = h0T + p*HB;  float* h0w = h0T + (p^1)*HB;
        float* h1r = h1T + p*HB;  float* h1w = h1T + (p^1)*HB;

        if (has_attn) {
            // ---- Q phase: q[b][j] = attW_q[j] . h1_prev[b] ----
            {
                ull aq = 0ull;
                ulonglong2 r[4];
                ld_chunk(h1r, h1r + 8192, 0, tid, r);
                st_chunk(Xs, 0, tid, r);
                __syncthreads();
                for (int c = 0; c < 4; c++) {
                    if (c < 3) ld_chunk(h1r, h1r + 8192, c+1, tid, r);
                    const ull* xb = Xs + (size_t)(c & 1)*2048 + grp*1024 + lane;
                    int kpb = grp*128 + c*32;
                    #pragma unroll
                    for (int kk = 0; kk < 32; kk++)
                        FMA2(aq, xb[kk*32], qwu[(kpb + kk)*4 + jj]);
                    if (c < 3) st_chunk(Xs, (c+1) & 1, tid, r);
                    __syncthreads();
                }
                if (grp == 1) Red[jj][0][lane] = aq;
                __syncthreads();
                if (grp == 0) {
                    float2 A = up2(aq), R = up2(Red[jj][0][lane]);
                    qT[((j>>1)*64) + lane*2 + (j&1)] = A.x + A.y + R.x + R.y;
                }
            }
            gridbar(mygen);
            // ---- ATTN phase: blocks 0..31, b = bid ----
            if (bid < 32) {
                const int b = bid;
                const ull* qu = (const ull*)qT + b;
                ((ull*)qs)[tid] = ldcg64(qu + (size_t)tid*32);
                __syncthreads();
                for (int tt = warp; tt < T; tt += 8) {
                    if (mask[b*T + tt]) { if (lane == 0) sc[tt] = -1e9f; }
                    else {
                        float acc = 0.f;
                        const float* kr = Kpre + ((size_t)b*T + tt)*H;
                        #pragma unroll 4
                        for (int j2 = lane; j2 < H; j2 += 32) acc += tanhf(qs[j2] + kr[j2]) * attv[j2];
                        for (int o = 16; o; o >>= 1) acc += __shfl_xor_sync(0xffffffffu, acc, o);
                        if (lane == 0) sc[tt] = acc;
                    }
                }
                __syncthreads();
                if (tid < 32) {
                    float v = sc[tid], m = v;
                    for (int o = 16; o; o >>= 1) m = fmaxf(m, __shfl_xor_sync(0xffffffffu, m, o));
                    float e = expf(v - m), ss = e;
                    for (int o = 16; o; o >>= 1) ss += __shfl_xor_sync(0xffffffffu, ss, o);
                    sc[tid] = e / ss;
                }
                __syncthreads();
                #pragma unroll
                for (int h2 = 0; h2 < 2; h2++) {
                    int j2 = tid + h2*256;
                    float acc = 0.f;
                    const float* eo = Eout + (size_t)b*T*H + j2;
                    #pragma unroll
                    for (int t2 = 0; t2 < T; t2++) acc += sc[t2] * eo[(size_t)t2*H];
                    ctxT[((j2>>1)*64) + b*2 + (j2&1)] = acc;
                }
            }
            gridbar(mygen);
            // ---- L0: grp0 src = ctx (PC weights), grp1 src = h0 (PH0) ----
            lstm_phase2(wv0g, 256, ctxT, h0r, Xs, G0 + (size_t)t*B*4*H, 0,
                        Red, tid, jj, grp, lane, j, c0, h0w, (float*)0, 0);
        } else {
            // ---- L0 (s=0): ctx == 0 -> h0-only, 128 kp per grp ----
            lstm_phase2(wv0g, 128, h0r, h0r + 8192, Xs, G0 + (size_t)t*B*4*H, 0,
                        Red, tid, jj, grp, lane, j, c0, h0w, (float*)0, 0);
        }
        gridbar(mygen);
        // ---- L1: grp0 src = h0(new) (PX1), grp1 src = h1 (PH1) ----
        lstm_phase2(wv1g, 256, h0w, h1r, Xs, biasL1, 1,
                    Red, tid, jj, grp, lane, j, c1, h1w, Dout + (size_t)t*B*H, H);
        gridbar(mygen);
    }
}

// ---------------- persistent encoder kernel ----------------
#define ENC_RED_OFF 98304
#define ENC_XS_OFF  (ENC_RED_OFF + 4096)
#define SMEM_ENC    (ENC_XS_OFF + 32768)
__global__ __launch_bounds__(256, 1) void k_enc(
    const float* __restrict__ G0, const float* __restrict__ biasL1,
    const float* __restrict__ PH0, const float* __restrict__ PX1, const float* __restrict__ PH1,
    float* h0T, float* h1T, float* c0, float* c1, float* Eraw)
{
    extern __shared__ char smem[];
    float4* W4 = (float4*)smem;
    ull (*Red)[4][32] = (ull (*)[4][32])(smem + ENC_RED_OFF);
    ull*  Xs  = (ull*)(smem + ENC_XS_OFF);

    int tid = threadIdx.x, warp = tid >> 5, lane = tid & 31;
    int jj = warp & 3, grp = warp >> 2;
    int bid = blockIdx.x;
    int jb = bid*4, j = jb + jj;
    unsigned mygen = ld_acq(&g_gen);

    {
        const float4* s4 = ((const float4*)PH0) + (size_t)bid*2048;
        for (int i = tid; i < 2048; i += 256) W4[i] = s4[i];
        const float* srcs[2] = { PX1, PH1 };
        for (int m = 0; m < 2; m++) {
            const float4* s2 = ((const float4*)srcs[m]) + (size_t)bid*2048;
            float4* d4 = W4 + 2048 + (size_t)m*2048;
            for (int i = tid; i < 2048; i += 256) d4[i] = s2[i];
        }
    }
    __syncthreads();
    // enc L0: one slab; warp reads jj row, grp takes upper/lower 128 kp of that row
    const ulonglong2* wv0g = (const ulonglong2*)(W4 + (size_t)jj*512 + (size_t)grp*256);
    // enc L1: [PX1 | PH1]; grp selects slab, jj selects row
    const ulonglong2* wv1g = (const ulonglong2*)(W4 + 2048 + (size_t)grp*2048 + (size_t)jj*512);

    for (int t = 0; t < T; t++) {
        int p = t & 1;
        float* h0r = h0T + p*HB;  float* h0w = h0T + (p^1)*HB;
        float* h1r = h1T + p*HB;  float* h1w = h1T + (p^1)*HB;
        lstm_phase2(wv0g, 128, h0r, h0r + 8192, Xs,
                    G0 + (size_t)t*B*4*H, 0,
                    Red, tid, jj, grp, lane, j, c0, h0w, (float*)0, 0);
        gridbar(mygen);
        lstm_phase2(wv1g, 256, h0w, h1r, Xs, biasL1, 1,
                    Red, tid, jj, grp, lane, j, c1, h1w, Eraw + (size_t)t*H, T*H);
        gridbar(mygen);
    }
}

// ---------------- host orchestration ----------------
extern "C" void kernel_launch(void* const* d_in, const int* in_sizes, int n_in,
                              void* d_out, int out_size) {
    const int*   inputs   = (const int*)d_in[0];
    const int*   targets  = (const int*)d_in[1];
    const float* enc_emb  = (const float*)d_in[2];
    const float* enc_Wih  = (const float*)d_in[3];
    const float* enc_Whh  = (const float*)d_in[4];
    const float* enc_bias = (const float*)d_in[5];
    const float* enc_ln_g = (const float*)d_in[6];
    const float* enc_ln_b = (const float*)d_in[7];
    const float* dec_emb  = (const float*)d_in[8];
    const float* att_W    = (const float*)d_in[9];
    const float* att_b    = (const float*)d_in[10];
    const float* att_v    = (const float*)d_in[11];
    const float* dec_Wih0 = (const float*)d_in[12];
    const float* dec_Wih1 = (const float*)d_in[13];
    const float* dec_Whh  = (const float*)d_in[14];
    const float* dec_bias = (const float*)d_in[15];
    const float* dec_ln_g = (const float*)d_in[16];
    const float* dec_ln_b = (const float*)d_in[17];
    const float* fc_W     = (const float*)d_in[18];
    const float* fc_b     = (const float*)d_in[19];
    float* out = (float*)d_out;

    static cudaStream_t s2 = nullptr;
    static cudaEvent_t evGath = nullptr;
    static cudaEvent_t evD[NS];     // G0D slices 1..5
    static cudaEvent_t evE[NS];     // G0E slices 0..4
    static cudaEvent_t evA[NS];
    static cudaEvent_t evEnd = nullptr;
    if (!s2) {
        cudaStreamCreateWithFlags(&s2, cudaStreamNonBlocking);
        cudaEventCreateWithFlags(&evGath, cudaEventDisableTiming);
        for (int i = 0; i < NS; i++) {
            cudaEventCreateWithFlags(&evD[i], cudaEventDisableTiming);
            cudaEventCreateWithFlags(&evE[i], cudaEventDisableTiming);
            cudaEventCreateWithFlags(&evA[i], cudaEventDisableTiming);
        }
        cudaEventCreateWithFlags(&evEnd, cudaEventDisableTiming);
    }

    float* buf = nullptr;
    cudaGetSymbolAddress((void**)&buf, g_buf);
    int* maskp = nullptr;
    cudaGetSymbolAddress((void**)&maskp, g_mask);

    float* CtxT = buf + OFF_CTXT;
    float* QT   = buf + OFF_QT;
    float* DH0T = buf + OFF_DH0T;
    float* DH1T = buf + OFF_DH1T;
    float* EH0T = buf + OFF_EH0T;
    float* EH1T = buf + OFF_EH1T;
    float* DC0  = buf + OFF_DC0;
    float* DC1  = buf + OFF_DC1;
    float* EC0  = buf + OFF_EC0;
    float* EC1  = buf + OFF_EC1;
    float* XembD= buf + OFF_XEMBD;
    float* XembE= buf + OFF_XEMBE;
    float* G0D  = buf + OFF_G0D;
    float* G0E  = buf + OFF_G0E;
    float* Dout = buf + OFF_DOUT;      // 6 slices
    float* NormB= buf + OFF_NORM;      // 5 slices
    float* Eraw = buf + OFF_ERAW;
    float* Eout = buf + OFF_EOUT;
    float* Kpre = buf + OFF_KPRE;
    float* P_DL0C = buf + OFF_PACK + 0ull*PACK_SZ;
    float* P_DL0H = buf + OFF_PACK + 1ull*PACK_SZ;
    float* P_DL1X = buf + OFF_PACK + 2ull*PACK_SZ;
    float* P_DL1H = buf + OFF_PACK + 3ull*PACK_SZ;
    float* P_EL0H = buf + OFF_PACK + 4ull*PACK_SZ;
    float* P_EL1X = buf + OFF_PACK + 5ull*PACK_SZ;
    float* P_EL1H = buf + OFF_PACK + 6ull*PACK_SZ;

    cudaFuncSetAttribute(k_dec, cudaFuncAttributeMaxDynamicSharedMemorySize, SMEM_DEC);
    cudaFuncSetAttribute(k_enc, cudaFuncAttributeMaxDynamicSharedMemorySize, SMEM_ENC);

    // ---- main-stream prologue (k_dec s=0 is launch #6) ----
    k_packall<<<dim3(2, 512, 7), 128>>>(dec_Wih0, dec_Wih1, dec_Whh, enc_Wih, enc_Whh);
    k_zero<<<(ZERO_CNT + 255)/256, 256>>>();
    k_gather<<<NS*T*B, 128>>>(inputs, targets, dec_emb, XembD, 1);
    k_gather<<<(NS-1)*T*B, 128>>>(inputs, targets, enc_emb, XembE, 0);
    cudaEventRecord(evGath, 0);
    k_gemm2<<<dim3(16, 8), 256>>>(XembD, dec_Wih0, 2*H, dec_bias, G0D, 4*H, 0, 0);
    k_dec<<<NBLK, 256, SMEM_DEC>>>(G0D, dec_bias + 4*H,
                                   P_DL0C, P_DL0H, P_DL1X, P_DL1H,
                                   CtxT, DH0T, DH1T, DC0, DC1,
                                   QT, att_W, att_v, Kpre, Eout,
                                   maskp, Dout, 0);
    k_maskall<<<1, 32>>>(inputs, targets);

    // ---- side stream: remaining gate slices (overlap with dec0/enc0) ----
    cudaStreamWaitEvent(s2, evGath, 0);
    for (int s = 1; s < NS; s++) {
        k_gemm2<<<dim3(16, 8), 256, 0, s2>>>(XembD + (size_t)s*TBH, dec_Wih0, 2*H,
                                             dec_bias, G0D + (size_t)s*T*B*4*H, 4*H, 0, 0);
        cudaEventRecord(evD[s], s2);
    }
    for (int s = 0; s < NS-1; s++) {
        k_gemm2<<<dim3(16, 8), 256, 0, s2>>>(XembE + (size_t)s*TBH, enc_Wih, H,
                                             enc_bias, G0E + (size_t)s*T*B*4*H, 4*H, 0, 0);
        cudaEventRecord(evE[s], s2);
    }

    for (int s = 0; s < NS; s++) {
        if (s > 0) {
            cudaStreamWaitEvent(0, evD[s], 0);
            k_dec<<<NBLK, 256, SMEM_DEC>>>(G0D + (size_t)s*T*B*4*H, dec_bias + 4*H,
                                           P_DL0C, P_DL0H, P_DL1X, P_DL1H,
                                           CtxT, DH0T, DH1T, DC0, DC1,
                                           QT, att_W, att_v, Kpre, Eout,
                                           maskp + (s-1)*B*T,
                                           Dout + (size_t)s*TBH, 1);
            // LN + logits on the side stream, overlapped with subsequent enc/dec
            cudaEventRecord(evA[s], 0);
            cudaStreamWaitEvent(s2, evA[s], 0);
            k_ln<<<T*B, 128, 0, s2>>>(Dout + (size_t)s*TBH, NormB + (size_t)(s-1)*TBH,
                                      dec_ln_g, dec_ln_b);
            k_gemm2<<<dim3((V + 127)/128, 8), 256, 0, s2>>>(NormB + (size_t)(s-1)*TBH,
                                                            fc_W, H, fc_b, out, V, 1, s-1);
        }
        if (s < NS - 1) {
            cudaStreamWaitEvent(0, evE[s], 0);
            k_enc<<<NBLK, 256, SMEM_ENC>>>(G0E + (size_t)s*T*B*4*H, enc_bias + 4*H,
                                           P_EL0H, P_EL1X, P_EL1H,
                                           EH0T, EH1T, EC0, EC1, Eraw);
            k_ln<<<T*B, 128>>>(Eraw, Eout, enc_ln_g, enc_ln_b);
            k_gemm2<<<dim3(4, 8), 256>>>(Eout, att_W + H, 2*H, att_b, Kpre, H, 0, 0);
        }
    }
    // join side stream back into the main stream before graph end
    cudaEventRecord(evEnd, s2);
    cudaStreamWaitEvent(0, evEnd, 0);
}

// round 15
// speedup vs baseline: 1.0548x; 1.0548x over previous
#include <cuda_runtime.h>
#include <math.h>

#define H 512
#define B 32
#define T 32
#define V 6000
#define NS 6
#define HB (H*B)
#define NBLK 128
#define TBH (T*B*H)

typedef unsigned long long ull;

// ---------------- scratch layout (floats) ----------------
// Pair-transposed (PT) layout: float (b,k) at (k>>1)*64 + b*2 + (k&1)
// State parity convention: h(t) lives in buffer ((t+1)&1); initial zeros / inter-
// sentence handoff at parity 0 (matches k_dec's read-p / write-p^1 scheme).
#define OFF_CTXT 0
#define OFF_QT   (OFF_CTXT + HB)
#define OFF_DH0T (OFF_QT + HB)
#define OFF_DH1T (OFF_DH0T + 2*HB)
#define OFF_EH0T (OFF_DH1T + 2*HB)
#define OFF_EH1T (OFF_EH0T + 2*HB)
#define OFF_DC0  (OFF_EH1T + 2*HB)
#define OFF_DC1  (OFF_DC0 + HB)
#define OFF_EC0  (OFF_DC1 + HB)
#define OFF_EC1  (OFF_EC0 + HB)
#define ZERO_CNT (OFF_EC1 + HB)
#define OFF_XEMBD ZERO_CNT
#define OFF_XEMBE (OFF_XEMBD + 6*TBH)
#define OFF_G0D  (OFF_XEMBE + 5*TBH)
#define OFF_G0E  (OFF_G0D + 6*T*B*4*H)
#define OFF_DOUT (OFF_G0E + 5*T*B*4*H)   // 6 per-sentence slices
#define OFF_NORM (OFF_DOUT + 6*TBH)      // 5 slices
#define OFF_ERAW (OFF_NORM + 5*TBH)
#define OFF_EOUT (OFF_ERAW + TBH)
#define OFF_KPRE (OFF_EOUT + TBH)
#define OFF_PACK (OFF_KPRE + TBH)
#define PACK_SZ  (H*H*4)
#define N_PACK   7
#define BUF_TOTAL (OFF_PACK + (size_t)N_PACK*PACK_SZ)

__device__ __align__(256) float g_buf[BUF_TOTAL];
__device__ int   g_mask[(NS-1)*B*T];
__device__ unsigned g_gen;
__device__ unsigned g_arr[NBLK];

// ---------------- low-level helpers ----------------
#define FMA2(a,x,w) asm("fma.rn.f32x2 %0, %1, %2, %0;" : "+l"(a) : "l"(x), "l"(w))
__device__ __forceinline__ ull pk2(float lo, float hi) {
    ull r; asm("mov.b64 %0, {%1,%2};" : "=l"(r) : "f"(lo), "f"(hi)); return r;
}
__device__ __forceinline__ float2 up2(ull v) {
    float2 f; asm("mov.b64 {%0,%1}, %2;" : "=f"(f.x), "=f"(f.y) : "l"(v)); return f;
}
__device__ __forceinline__ float ldcgf(const float* p) {
    float v; asm volatile("ld.global.cg.f32 %0, [%1];" : "=f"(v) : "l"(p)); return v;
}
__device__ __forceinline__ ull ldcg64(const ull* p) {
    ull v; asm volatile("ld.global.cg.b64 %0, [%1];" : "=l"(v) : "l"(p)); return v;
}
__device__ __forceinline__ ulonglong2 ldcgv2(const ulonglong2* p) {
    ulonglong2 v;
    asm volatile("ld.global.cg.v2.u64 {%0,%1}, [%2];" : "=l"(v.x), "=l"(v.y) : "l"(p));
    return v;
}
__device__ __forceinline__ void st_rel(unsigned* p, unsigned v) {
    asm volatile("st.release.gpu.global.u32 [%0], %1;" :: "l"(p), "r"(v) : "memory");
}
__device__ __forceinline__ unsigned ld_acq(const unsigned* p) {
    unsigned v; asm volatile("ld.acquire.gpu.global.u32 %0, [%1];" : "=r"(v) : "l"(p) : "memory"); return v;
}

// ---------------- 2-hop grid barrier (monotonic generations; replay-safe) ----------------
__device__ __forceinline__ void gridbar(unsigned &mygen) {
    __syncthreads();
    mygen++;
    if (threadIdx.x == 0) st_rel(&g_arr[blockIdx.x], mygen);
    if (blockIdx.x == 0) {
        if (threadIdx.x < NBLK) {
            while ((int)(ld_acq(&g_arr[threadIdx.x]) - mygen) < 0) { }
        }
        __syncthreads();
        if (threadIdx.x == 0) st_rel(&g_gen, mygen);
    } else {
        if (threadIdx.x == 0) {
            while ((int)(ld_acq(&g_gen) - mygen) < 0) { __nanosleep(32); }
        }
        __syncthreads();
    }
}

// ---------------- zero recurrent state ----------------
__global__ void k_zero() {
    int i = blockIdx.x * 256 + threadIdx.x;
    if (i < ZERO_CNT) g_buf[i] = 0.0f;
}

// ---------------- fused pack: all 7 weight slabs in one launch (blockIdx.z selects) ----------------
__global__ void k_packall(const float* __restrict__ dWih0, const float* __restrict__ dWih1,
                          const float* __restrict__ dWhh,  const float* __restrict__ eWih,
                          const float* __restrict__ eWhh) {
    int kp = blockIdx.x * 128 + threadIdx.x;
    int j  = blockIdx.y;
    int z  = blockIdx.z;
    const float* W; int ldw;
    switch (z) {
        case 0: W = dWih0 + H;       ldw = 2*H; break;  // P_DL0C (ctx cols)
        case 1: W = dWhh;            ldw = H;   break;  // P_DL0H
        case 2: W = dWih1;           ldw = H;   break;  // P_DL1X
        case 3: W = dWhh + 4*H*H;    ldw = H;   break;  // P_DL1H
        case 4: W = eWhh;            ldw = H;   break;  // P_EL0H
        case 5: W = eWih + 4*H*H;    ldw = H;   break;  // P_EL1X
        default:W = eWhh + 4*H*H;    ldw = H;   break;  // P_EL1H
    }
    float* P = g_buf + OFF_PACK + (size_t)z*PACK_SZ;
    float* o = P + ((size_t)j*256 + kp)*8;
    #pragma unroll
    for (int g = 0; g < 4; g++) {
        o[g*2+0] = W[(size_t)(g*H + j) * ldw + 2*kp];
        o[g*2+1] = W[(size_t)(g*H + j) * ldw + 2*kp + 1];
    }
}

// ---------------- batched embedding gather (all sentences) ----------------
__global__ void k_gather(const int* __restrict__ inputs, const int* __restrict__ targets,
                         const float* __restrict__ emb, float* __restrict__ X, int is_dec) {
    int row = blockIdx.x;          // s*1024 + t*32 + b
    int s = row >> 10, t = (row >> 5) & 31, b = row & 31;
    int tok;
    if (is_dec) {
        if (t == 0) tok = 1;
        else tok = (s == 0) ? inputs[b*192 + (t-1)] : targets[b*160 + (s-1)*32 + (t-1)];
    } else {
        tok = (s == 0) ? inputs[b*192 + t] : targets[b*160 + (s-1)*32 + t];
    }
    const float4* e = (const float4*)(emb + (size_t)tok * H);
    float4* o = (float4*)(X + (size_t)row * H);
    for (int i = threadIdx.x; i < H/4; i += 128) o[i] = e[i];
}

// ---------------- all masks upfront ----------------
__global__ void k_maskall(const int* __restrict__ inputs, const int* __restrict__ targets) {
    int b = threadIdx.x;
    if (b >= B) return;
    for (int s = 0; s < NS-1; s++) {
        int seen = 0;
        for (int t = 0; t < T; t++) {
            g_mask[s*B*T + b*T + t] = seen;
            int tok = (s == 0) ? inputs[b*192 + t] : targets[b*160 + (s-1)*32 + t];
            if (tok == 2 || tok == 3) seen = 1;
        }
    }
}

// ---------------- SGEMM 128x128, 8x8 micro, FFMA2, double-buffered ----------------
__global__ __launch_bounds__(256) void k_gemm2(
    const float* __restrict__ A,
    const float* __restrict__ W, int ldw,
    const float* __restrict__ bias,
    float* __restrict__ C, int N, int mode, int spar)
{
    __shared__ float As[2][16][136];
    __shared__ float Bs[2][16][136];
    int tid = threadIdx.x;
    int m0 = blockIdx.y*128, n0 = blockIdx.x*128;
    int lr = tid >> 1, lc = (tid & 1)*8;
    int ty = tid >> 4, tx = tid & 15;
    ull acc2[8][4];
    #pragma unroll
    for (int i = 0; i < 8; i++)
        #pragma unroll
        for (int jp = 0; jp < 4; jp++) acc2[i][jp] = 0ull;

    const float* Arow = A + (size_t)(m0 + lr) * 512;
    bool bvalid = (n0 + lr) < N;
    const float* Wrow = W + (size_t)(bvalid ? (n0 + lr) : 0) * ldw;
    float4 z4 = make_float4(0.f, 0.f, 0.f, 0.f);

    float4 pa0 = *(const float4*)(Arow + lc);
    float4 pa1 = *(const float4*)(Arow + lc + 4);
    float4 pb0 = bvalid ? *(const float4*)(Wrow + lc) : z4;
    float4 pb1 = bvalid ? *(const float4*)(Wrow + lc + 4) : z4;
    As[0][lc+0][lr]=pa0.x; As[0][lc+1][lr]=pa0.y; As[0][lc+2][lr]=pa0.z; As[0][lc+3][lr]=pa0.w;
    As[0][lc+4][lr]=pa1.x; As[0][lc+5][lr]=pa1.y; As[0][lc+6][lr]=pa1.z; As[0][lc+7][lr]=pa1.w;
    Bs[0][lc+0][lr]=pb0.x; Bs[0][lc+1][lr]=pb0.y; Bs[0][lc+2][lr]=pb0.z; Bs[0][lc+3][lr]=pb0.w;
    Bs[0][lc+4][lr]=pb1.x; Bs[0][lc+5][lr]=pb1.y; Bs[0][lc+6][lr]=pb1.z; Bs[0][lc+7][lr]=pb1.w;
    __syncthreads();

    int buf = 0;
    for (int k0 = 16; k0 <= 512; k0 += 16) {
        bool more = k0 < 512;
        if (more) {
            pa0 = *(const float4*)(Arow + k0 + lc);
            pa1 = *(const float4*)(Arow + k0 + lc + 4);
            pb0 = bvalid ? *(const float4*)(Wrow + k0 + lc) : z4;
            pb1 = bvalid ? *(const float4*)(Wrow + k0 + lc + 4) : z4;
        }
        #pragma unroll
        for (int k = 0; k < 16; k++) {
            float4 a0 = *(const float4*)&As[buf][k][ty*8];
            float4 a1 = *(const float4*)&As[buf][k][ty*8+4];
            ulonglong2 b0 = *(const ulonglong2*)&Bs[buf][k][tx*8];
            ulonglong2 b1 = *(const ulonglong2*)&Bs[buf][k][tx*8+4];
            float av[8] = {a0.x,a0.y,a0.z,a0.w,a1.x,a1.y,a1.z,a1.w};
            #pragma unroll
            for (int i = 0; i < 8; i++) {
                ull ad = pk2(av[i], av[i]);
                FMA2(acc2[i][0], ad, b0.x);
                FMA2(acc2[i][1], ad, b0.y);
                FMA2(acc2[i][2], ad, b1.x);
                FMA2(acc2[i][3], ad, b1.y);
            }
        }
        if (more) {
            int nb = buf ^ 1;
            As[nb][lc+0][lr]=pa0.x; As[nb][lc+1][lr]=pa0.y; As[nb][lc+2][lr]=pa0.z; As[nb][lc+3][lr]=pa0.w;
            As[nb][lc+4][lr]=pa1.x; As[nb][lc+5][lr]=pa1.y; As[nb][lc+6][lr]=pa1.z; As[nb][lc+7][lr]=pa1.w;
            Bs[nb][lc+0][lr]=pb0.x; Bs[nb][lc+1][lr]=pb0.y; Bs[nb][lc+2][lr]=pb0.z; Bs[nb][lc+3][lr]=pb0.w;
            Bs[nb][lc+4][lr]=pb1.x; Bs[nb][lc+5][lr]=pb1.y; Bs[nb][lc+6][lr]=pb1.z; Bs[nb][lc+7][lr]=pb1.w;
        }
        __syncthreads();
        buf ^= 1;
    }
    #pragma unroll
    for (int i = 0; i < 8; i++) {
        int m = m0 + ty*8 + i;
        #pragma unroll
        for (int jp = 0; jp < 4; jp++) {
            float2 p = up2(acc2[i][jp]);
            int n = n0 + tx*8 + jp*2;
            #pragma unroll
            for (int e = 0; e < 2; e++) {
                int ne = n + e;
                if (ne < N) {
                    float v = (e ? p.y : p.x) + bias[ne];
                    if (mode == 0) C[(size_t)m*N + ne] = v;
                    else {
                        int t = (m >> 5) & 31, b = m & 31;
                        C[(((size_t)b*5 + spar)*32 + t)*(size_t)V + ne] = v;
                    }
                }
            }
        }
    }
}

// ---------------- layernorm ----------------
__global__ void k_ln(const float* __restrict__ in, float* __restrict__ out,
                     const float* __restrict__ g, const float* __restrict__ bb) {
    int row = blockIdx.x, tid = threadIdx.x;
    const float* x = in + (size_t)row * H;
    float v[4], s = 0.f;
    #pragma unroll
    for (int i = 0; i < 4; i++) { v[i] = x[tid + i*128]; s += v[i]; }
    __shared__ float rs[4];
    for (int o = 16; o; o >>= 1) s += __shfl_xor_sync(0xffffffffu, s, o);
    int warp = tid >> 5, lane = tid & 31;
    if (lane == 0) rs[warp] = s;
    __syncthreads();
    float mean = (rs[0] + rs[1] + rs[2] + rs[3]) / (float)H;
    __syncthreads();
    float s2 = 0.f;
    #pragma unroll
    for (int i = 0; i < 4; i++) { float d = v[i] - mean; s2 += d*d; }
    for (int o = 16; o; o >>= 1) s2 += __shfl_xor_sync(0xffffffffu, s2, o);
    if (lane == 0) rs[warp] = s2;
    __syncthreads();
    float var = (rs[0] + rs[1] + rs[2] + rs[3]) / (float)H;
    float inv = rsqrtf(var + 1e-5f);
    #pragma unroll
    for (int i = 0; i < 4; i++) {
        int c = tid + i*128;
        out[(size_t)row*H + c] = (v[i] - mean) * inv * g[c] + bb[c];
    }
}

// ---------------- cooperative chunk staging (block-cooperative; x0/x1 uniform) ----------------
__device__ __forceinline__ void ld_chunk(const float* x0, const float* x1, int c, int tid,
                                         ulonglong2* r) {
    #pragma unroll
    for (int q = 0; q < 4; q++) {
        int idx = tid + q*256;
        const float* src = (idx >> 9) ? x1 : x0;
        int off = idx & 511;
        r[q] = ldcgv2((const ulonglong2*)src + (size_t)c*512 + off);
    }
}
__device__ __forceinline__ void st_chunk(ull* Xs, int b, int tid, const ulonglong2* r) {
    ulonglong2* dst = (ulonglong2*)(Xs + (size_t)b*2048);
    #pragma unroll
    for (int q = 0; q < 4; q++) dst[tid + q*256] = r[q];
}

// ---------------- fused LSTM phase: smem-staged x, smem weights, f32x2 ----------------
__device__ __forceinline__ void lstm_phase2(
    const ulonglong2* wv, int nkp,
    const float* x0, const float* x1, ull* Xs,
    const float* base, int base_vec,
    ull (*Red)[4][32],
    int tid, int jj, int grp, int lane, int j,
    float* cst, float* hT, float* extraBase, int extraStride)
{
    ull ai, af, ag, ao;
    float cold = 0.f;
    if (grp == 0) {
        cold = ldcgf(cst + (size_t)lane*H + j);
        float bi, bf, bg, bo;
        if (base_vec) { bi = base[j]; bf = base[H+j]; bg = base[2*H+j]; bo = base[3*H+j]; }
        else {
            const float* r = base + (size_t)lane * (4*H);
            bi = r[j]; bf = r[H+j]; bg = r[2*H+j]; bo = r[3*H+j];
        }
        ai = pk2(bi, 0.f); af = pk2(bf, 0.f); ag = pk2(bg, 0.f); ao = pk2(bo, 0.f);
    } else { ai = af = ag = ao = 0ull; }

    int nc = nkp >> 5;
    ulonglong2 r[4];
    ld_chunk(x0, x1, 0, tid, r);
    st_chunk(Xs, 0, tid, r);
    __syncthreads();
    for (int c = 0; c < nc; c++) {
        if (c + 1 < nc) ld_chunk(x0, x1, c+1, tid, r);
        const ull* xb = Xs + (size_t)(c & 1)*2048 + grp*1024 + lane;
        const ulonglong2* wc = wv + (size_t)c*64;
        #pragma unroll
        for (int kp = 0; kp < 32; kp++) {
            ull x2 = xb[kp*32];
            ulonglong2 wa = wc[kp*2];
            ulonglong2 wb = wc[kp*2 + 1];
            FMA2(ai, x2, wa.x); FMA2(af, x2, wa.y);
            FMA2(ag, x2, wb.x); FMA2(ao, x2, wb.y);
        }
        if (c + 1 < nc) st_chunk(Xs, (c+1) & 1, tid, r);
        __syncthreads();
    }
    if (grp == 1) {
        Red[jj][0][lane] = ai; Red[jj][1][lane] = af;
        Red[jj][2][lane] = ag; Red[jj][3][lane] = ao;
    }
    __syncthreads();
    if (grp == 0) {
        float2 A, R;
        A = up2(ai); R = up2(Red[jj][0][lane]); float gi = A.x + A.y + R.x + R.y;
        A = up2(af); R = up2(Red[jj][1][lane]); float gf = A.x + A.y + R.x + R.y;
        A = up2(ag); R = up2(Red[jj][2][lane]); float gg = A.x + A.y + R.x + R.y;
        A = up2(ao); R = up2(Red[jj][3][lane]); float go = A.x + A.y + R.x + R.y;
        float si = 1.f / (1.f + expf(-gi));
        float sf = 1.f / (1.f + expf(-gf));
        float so = 1.f / (1.f + expf(-go));
        float c2 = sf * cold + si * tanhf(gg);
        float h2 = so * tanhf(c2);
        cst[(size_t)lane*H + j] = c2;
        hT[((j>>1)*64) + lane*2 + (j&1)] = h2;
        if (extraBase) extraBase[(size_t)lane*extraStride + j] = h2;
    }
}

// ---------------- merged L0/L1 pipelined kernel (encoder + attention-free decoder) ----------------
// Phase ph (0..T): computes L0(t=ph) [reads h0(ph-1)] and L1(t=ph-1) [reads h0(ph-1), h1(ph-2)].
// 33 barriers/sentence instead of 64. c-state lives in registers for the whole sentence.
// W4 layout: [PH0 | PX1 | PH1] slabs (2048 float4 each per block).
#define ENCM_RED_OFF 98304
#define ENCM_XS_OFF  (ENCM_RED_OFF + 8192)
#define SMEM_ENCM    (ENCM_XS_OFF + 32768)
__global__ __launch_bounds__(256, 1) void k_encm(
    const float* __restrict__ G0, const float* __restrict__ biasL1,
    const float* __restrict__ PH0, const float* __restrict__ PX1, const float* __restrict__ PH1,
    float* h0T, float* h1T, float* c0, float* c1,
    float* outB, int strideT, int strideB)
{
    extern __shared__ char smem[];
    float4* W4 = (float4*)smem;
    ull* Red2 = (ull*)(smem + ENCM_RED_OFF);   // [2][4][4][32] flat
    ull* Xs   = (ull*)(smem + ENCM_XS_OFF);

    int tid = threadIdx.x, warp = tid >> 5, lane = tid & 31;
    int jj = warp & 3, grp = warp >> 2;
    int bid = blockIdx.x;
    int jb = bid*4, j = jb + jj;
    unsigned mygen = ld_acq(&g_gen);

    {
        const float* srcs[3] = { PH0, PX1, PH1 };
        for (int m = 0; m < 3; m++) {
            const float4* s4 = ((const float4*)srcs[m]) + (size_t)bid*2048;
            float4* d4 = W4 + (size_t)m*2048;
            for (int i = tid; i < 2048; i += 256) d4[i] = s4[i];
        }
    }
    __syncthreads();
    const ulonglong2* wL0  = (const ulonglong2*)(W4 + (size_t)jj*512);
    const ulonglong2* wL1x = (const ulonglong2*)(W4 + 2048 + (size_t)jj*512);
    const ulonglong2* wL1h = (const ulonglong2*)(W4 + 4096 + (size_t)jj*512);

    float c0r = 0.f, c1r = 0.f;
    if (grp == 0) {
        c0r = ldcgf(c0 + (size_t)lane*H + j);
        c1r = ldcgf(c1 + (size_t)lane*H + j);
    }

    for (int ph = 0; ph <= T; ph++) {
        int doL0 = (ph < T), doL1 = (ph >= 1);
        const float* h0src = h0T + (size_t)(ph & 1)*HB;        // h0(ph-1)
        const float* h1src = h1T + (size_t)((ph + 1) & 1)*HB;  // h1(ph-2)
        ull l0[4] = {0ull,0ull,0ull,0ull};
        ull l1[4] = {0ull,0ull,0ull,0ull};

        ulonglong2 r[4];
        ld_chunk(h0src, h1src, 0, tid, r);
        st_chunk(Xs, 0, tid, r);
        __syncthreads();
        for (int c = 0; c < 8; c++) {
            if (c + 1 < 8) ld_chunk(h0src, h1src, c+1, tid, r);
            const ull* xh0 = Xs + (size_t)(c & 1)*2048 + lane;
            const ull* xh1 = xh0 + 1024;
            int kpb = c*32;
            if (grp == 0) {
                #pragma unroll
                for (int kk = 0; kk < 32; kk++) {
                    ull x2 = xh0[kk*32];
                    int kp = kpb + kk;
                    if (doL1) {
                        ulonglong2 wa = wL1x[kp*2], wb = wL1x[kp*2+1];
                        FMA2(l1[0], x2, wa.x); FMA2(l1[1], x2, wa.y);
                        FMA2(l1[2], x2, wb.x); FMA2(l1[3], x2, wb.y);
                    }
                    if (doL0 && c < 4) {
                        ulonglong2 wa = wL0[kp*2], wb = wL0[kp*2+1];
                        FMA2(l0[0], x2, wa.x); FMA2(l0[1], x2, wa.y);
                        FMA2(l0[2], x2, wb.x); FMA2(l0[3], x2, wb.y);
                    }
                }
            } else {
                #pragma unroll
                for (int kk = 0; kk < 32; kk++) {
                    int kp = kpb + kk;
                    if (doL1) {
                        ull x2 = xh1[kk*32];
                        ulonglong2 wa = wL1h[kp*2], wb = wL1h[kp*2+1];
                        FMA2(l1[0], x2, wa.x); FMA2(l1[1], x2, wa.y);
                        FMA2(l1[2], x2, wb.x); FMA2(l1[3], x2, wb.y);
                    }
                    if (doL0 && c >= 4) {
                        ull x2 = xh0[kk*32];
                        ulonglong2 wa = wL0[kp*2], wb = wL0[kp*2+1];
                        FMA2(l0[0], x2, wa.x); FMA2(l0[1], x2, wa.y);
                        FMA2(l0[2], x2, wb.x); FMA2(l0[3], x2, wb.y);
                    }
                }
            }
            if (c + 1 < 8) st_chunk(Xs, (c+1) & 1, tid, r);
            __syncthreads();
        }

        if (grp == 1) {
            #pragma unroll
            for (int g = 0; g < 4; g++) {
                Red2[((0*4 + jj)*4 + g)*32 + lane] = l0[g];
                Red2[((1*4 + jj)*4 + g)*32 + lane] = l1[g];
            }
        }
        __syncthreads();
        if (grp == 0) {
            if (doL1) {
                float gg[4];
                #pragma unroll
                for (int g = 0; g < 4; g++) {
                    float2 A = up2(l1[g]);
                    float2 R = up2(Red2[((1*4 + jj)*4 + g)*32 + lane]);
                    gg[g] = A.x + A.y + R.x + R.y + biasL1[g*H + j];
                }
                float si = 1.f/(1.f + expf(-gg[0]));
                float sf = 1.f/(1.f + expf(-gg[1]));
                float so = 1.f/(1.f + expf(-gg[3]));
                c1r = sf*c1r + si*tanhf(gg[2]);
                float h1v = so*tanhf(c1r);
                h1T[(size_t)(ph & 1)*HB + ((j>>1)*64) + lane*2 + (j&1)] = h1v;   // h1(ph-1)
                outB[(size_t)(ph-1)*strideT + (size_t)lane*strideB + j] = h1v;
            }
            if (doL0) {
                const float* rb = G0 + (size_t)ph*B*4*H + (size_t)lane*4*H;
                float gg[4];
                #pragma unroll
                for (int g = 0; g < 4; g++) {
                    float2 A = up2(l0[g]);
                    float2 R = up2(Red2[((0*4 + jj)*4 + g)*32 + lane]);
                    gg[g] = A.x + A.y + R.x + R.y + rb[g*H + j];
                }
                float si = 1.f/(1.f + expf(-gg[0]));
                float sf = 1.f/(1.f + expf(-gg[1]));
                float so = 1.f/(1.f + expf(-gg[3]));
                c0r = sf*c0r + si*tanhf(gg[2]);
                float h0v = so*tanhf(c0r);
                h0T[(size_t)((ph + 1) & 1)*HB + ((j>>1)*64) + lane*2 + (j&1)] = h0v;  // h0(ph)
            }
        }
        gridbar(mygen);
    }
    if (grp == 0) {
        c0[(size_t)lane*H + j] = c0r;
        c1[(size_t)lane*H + j] = c1r;
    }
}

// ---------------- persistent decoder kernel (attention sentences) ----------------
#define DEC_QW_OFF  131072
#define DEC_QS_OFF  (DEC_QW_OFF + 8192)
#define DEC_SC_OFF  (DEC_QS_OFF + 2048)
#define DEC_RED_OFF (DEC_SC_OFF + 128)
#define DEC_XS_OFF  (DEC_RED_OFF + 4096)
#define SMEM_DEC    (DEC_XS_OFF + 32768)
__global__ __launch_bounds__(256, 1) void k_dec(
    const float* __restrict__ G0, const float* __restrict__ biasL1,
    const float* __restrict__ PC, const float* __restrict__ PH0,
    const float* __restrict__ PX1, const float* __restrict__ PH1,
    float* ctxT, float* h0T, float* h1T, float* c0, float* c1,
    float* qT, const float* __restrict__ attW, const float* __restrict__ attv,
    const float* __restrict__ Kpre, const float* __restrict__ Eout,
    const int* __restrict__ mask,
    float* Dout)
{
    extern __shared__ char smem[];
    float4* W4 = (float4*)smem;
    ull*  Qw  = (ull*)(smem + DEC_QW_OFF);
    float* qs = (float*)(smem + DEC_QS_OFF);
    float* sc = (float*)(smem + DEC_SC_OFF);
    ull (*Red)[4][32] = (ull (*)[4][32])(smem + DEC_RED_OFF);
    ull*  Xs  = (ull*)(smem + DEC_XS_OFF);

    int tid = threadIdx.x, warp = tid >> 5, lane = tid & 31;
    int jj = warp & 3, grp = warp >> 2;
    int bid = blockIdx.x;
    int jb = bid*4, j = jb + jj;
    unsigned mygen = ld_acq(&g_gen);

    {
        const float* srcs[4] = { PC, PH0, PX1, PH1 };
        for (int m = 0; m < 4; m++) {
            const float4* s4 = ((const float4*)srcs[m]) + (size_t)bid*2048;
            float4* d4 = W4 + (size_t)m*2048;
            for (int i = tid; i < 2048; i += 256) d4[i] = s4[i];
        }
        for (int i = tid; i < 1024; i += 256) {
            int kp = i >> 2, jl = i & 3;
            Qw[i] = *(const ull*)(attW + (size_t)(jb + jl)*1024 + kp*2);
        }
    }
    __syncthreads();
    const ulonglong2* wv0g = (const ulonglong2*)(W4 + (size_t)grp*2048 + (size_t)jj*512);
    const ulonglong2* wv1g = (const ulonglong2*)(W4 + 4096 + (size_t)grp*2048 + (size_t)jj*512);
    const ull* qwu = Qw;

    for (int t = 0; t < T; t++) {
        int p = t & 1;
        float* h0r = h0T + p*HB;  float* h0w = h0T + (p^1)*HB;
        float* h1r = h1T + p*HB;  float* h1w = h1T + (p^1)*HB;

        // ---- Q phase: q[b][j] = attW_q[j] . h1_prev[b] ----
        {
            ull aq = 0ull;
            ulonglong2 r[4];
            ld_chunk(h1r, h1r + 8192, 0, tid, r);
            st_chunk(Xs, 0, tid, r);
            __syncthreads();
            for (int c = 0; c < 4; c++) {
                if (c < 3) ld_chunk(h1r, h1r + 8192, c+1, tid, r);
                const ull* xb = Xs + (size_t)(c & 1)*2048 + grp*1024 + lane;
                int kpb = grp*128 + c*32;
                #pragma unroll
                for (int kk = 0; kk < 32; kk++)
                    FMA2(aq, xb[kk*32], qwu[(kpb + kk)*4 + jj]);
                if (c < 3) st_chunk(Xs, (c+1) & 1, tid, r);
                __syncthreads();
            }
            if (grp == 1) Red[jj][0][lane] = aq;
            __syncthreads();
            if (grp == 0) {
                float2 A = up2(aq), R = up2(Red[jj][0][lane]);
                qT[((j>>1)*64) + lane*2 + (j&1)] = A.x + A.y + R.x + R.y;
            }
        }
        gridbar(mygen);
        // ---- ATTN phase: blocks 0..31, b = bid ----
        if (bid < 32) {
            const int b = bid;
            const ull* qu = (const ull*)qT + b;
            ((ull*)qs)[tid] = ldcg64(qu + (size_t)tid*32);
            __syncthreads();
            for (int tt = warp; tt < T; tt += 8) {
                if (mask[b*T + tt]) { if (lane == 0) sc[tt] = -1e9f; }
                else {
                    float acc = 0.f;
                    const float* kr = Kpre + ((size_t)b*T + tt)*H;
                    #pragma unroll 4
                    for (int j2 = lane; j2 < H; j2 += 32) acc += tanhf(qs[j2] + kr[j2]) * attv[j2];
                    for (int o = 16; o; o >>= 1) acc += __shfl_xor_sync(0xffffffffu, acc, o);
                    if (lane == 0) sc[tt] = acc;
                }
            }
            __syncthreads();
            if (tid < 32) {
                float v = sc[tid], m = v;
                for (int o = 16; o; o >>= 1) m = fmaxf(m, __shfl_xor_sync(0xffffffffu, m, o));
                float e = expf(v - m), ss = e;
                for (int o = 16; o; o >>= 1) ss += __shfl_xor_sync(0xffffffffu, ss, o);
                sc[tid] = e / ss;
            }
            __syncthreads();
            #pragma unroll
            for (int h2 = 0; h2 < 2; h2++) {
                int j2 = tid + h2*256;
                float acc = 0.f;
                const float* eo = Eout + (size_t)b*T*H + j2;
                #pragma unroll
                for (int t2 = 0; t2 < T; t2++) acc += sc[t2] * eo[(size_t)t2*H];
                ctxT[((j2>>1)*64) + b*2 + (j2&1)] = acc;
            }
        }
        gridbar(mygen);
        // ---- L0: grp0 src = ctx (PC weights), grp1 src = h0 (PH0) ----
        lstm_phase2(wv0g, 256, ctxT, h0r, Xs, G0 + (size_t)t*B*4*H, 0,
                    Red, tid, jj, grp, lane, j, c0, h0w, (float*)0, 0);
        gridbar(mygen);
        // ---- L1: grp0 src = h0(new) (PX1), grp1 src = h1 (PH1) ----
        lstm_phase2(wv1g, 256, h0w, h1r, Xs, biasL1, 1,
                    Red, tid, jj, grp, lane, j, c1, h1w, Dout + (size_t)t*B*H, H);
        gridbar(mygen);
    }
}

// ---------------- host orchestration ----------------
extern "C" void kernel_launch(void* const* d_in, const int* in_sizes, int n_in,
                              void* d_out, int out_size) {
    const int*   inputs   = (const int*)d_in[0];
    const int*   targets  = (const int*)d_in[1];
    const float* enc_emb  = (const float*)d_in[2];
    const float* enc_Wih  = (const float*)d_in[3];
    const float* enc_Whh  = (const float*)d_in[4];
    const float* enc_bias = (const float*)d_in[5];
    const float* enc_ln_g = (const float*)d_in[6];
    const float* enc_ln_b = (const float*)d_in[7];
    const float* dec_emb  = (const float*)d_in[8];
    const float* att_W    = (const float*)d_in[9];
    const float* att_b    = (const float*)d_in[10];
    const float* att_v    = (const float*)d_in[11];
    const float* dec_Wih0 = (const float*)d_in[12];
    const float* dec_Wih1 = (const float*)d_in[13];
    const float* dec_Whh  = (const float*)d_in[14];
    const float* dec_bias = (const float*)d_in[15];
    const float* dec_ln_g = (const float*)d_in[16];
    const float* dec_ln_b = (const float*)d_in[17];
    const float* fc_W     = (const float*)d_in[18];
    const float* fc_b     = (const float*)d_in[19];
    float* out = (float*)d_out;

    static cudaStream_t s2 = nullptr;
    static cudaEvent_t evGath = nullptr;
    static cudaEvent_t evD[NS];
    static cudaEvent_t evE[NS];
    static cudaEvent_t evA[NS];
    static cudaEvent_t evEnd = nullptr;
    if (!s2) {
        cudaStreamCreateWithFlags(&s2, cudaStreamNonBlocking);
        cudaEventCreateWithFlags(&evGath, cudaEventDisableTiming);
        for (int i = 0; i < NS; i++) {
            cudaEventCreateWithFlags(&evD[i], cudaEventDisableTiming);
            cudaEventCreateWithFlags(&evE[i], cudaEventDisableTiming);
            cudaEventCreateWithFlags(&evA[i], cudaEventDisableTiming);
        }
        cudaEventCreateWithFlags(&evEnd, cudaEventDisableTiming);
    }

    float* buf = nullptr;
    cudaGetSymbolAddress((void**)&buf, g_buf);
    int* maskp = nullptr;
    cudaGetSymbolAddress((void**)&maskp, g_mask);

    float* CtxT = buf + OFF_CTXT;
    float* QT   = buf + OFF_QT;
    float* DH0T = buf + OFF_DH0T;
    float* DH1T = buf + OFF_DH1T;
    float* EH0T = buf + OFF_EH0T;
    float* EH1T = buf + OFF_EH1T;
    float* DC0  = buf + OFF_DC0;
    float* DC1  = buf + OFF_DC1;
    float* EC0  = buf + OFF_EC0;
    float* EC1  = buf + OFF_EC1;
    float* XembD= buf + OFF_XEMBD;
    float* XembE= buf + OFF_XEMBE;
    float* G0D  = buf + OFF_G0D;
    float* G0E  = buf + OFF_G0E;
    float* Dout = buf + OFF_DOUT;
    float* NormB= buf + OFF_NORM;
    float* Eraw = buf + OFF_ERAW;
    float* Eout = buf + OFF_EOUT;
    float* Kpre = buf + OFF_KPRE;
    float* P_DL0C = buf + OFF_PACK + 0ull*PACK_SZ;
    float* P_DL0H = buf + OFF_PACK + 1ull*PACK_SZ;
    float* P_DL1X = buf + OFF_PACK + 2ull*PACK_SZ;
    float* P_DL1H = buf + OFF_PACK + 3ull*PACK_SZ;
    float* P_EL0H = buf + OFF_PACK + 4ull*PACK_SZ;
    float* P_EL1X = buf + OFF_PACK + 5ull*PACK_SZ;
    float* P_EL1H = buf + OFF_PACK + 6ull*PACK_SZ;

    cudaFuncSetAttribute(k_dec,  cudaFuncAttributeMaxDynamicSharedMemorySize, SMEM_DEC);
    cudaFuncSetAttribute(k_encm, cudaFuncAttributeMaxDynamicSharedMemorySize, SMEM_ENCM);

    // ---- main-stream prologue ----
    k_packall<<<dim3(2, 512, 7), 128>>>(dec_Wih0, dec_Wih1, dec_Whh, enc_Wih, enc_Whh);
    k_zero<<<(ZERO_CNT + 255)/256, 256>>>();
    k_gather<<<NS*T*B, 128>>>(inputs, targets, dec_emb, XembD, 1);
    k_gather<<<(NS-1)*T*B, 128>>>(inputs, targets, enc_emb, XembE, 0);
    cudaEventRecord(evGath, 0);
    k_gemm2<<<dim3(16, 8), 256>>>(XembD, dec_Wih0, 2*H, dec_bias, G0D, 4*H, 0, 0);
    // dec s=0 (no attention): merged pipelined kernel, 33 barriers
    k_encm<<<NBLK, 256, SMEM_ENCM>>>(G0D, dec_bias + 4*H,
                                     P_DL0H, P_DL1X, P_DL1H,
                                     DH0T, DH1T, DC0, DC1,
                                     Dout, B*H, H);
    k_maskall<<<1, 32>>>(inputs, targets);

    // ---- side stream: remaining gate slices (overlap with dec0/enc0) ----
    cudaStreamWaitEvent(s2, evGath, 0);
    for (int s = 1; s < NS; s++) {
        k_gemm2<<<dim3(16, 8), 256, 0, s2>>>(XembD + (size_t)s*TBH, dec_Wih0, 2*H,
                                             dec_bias, G0D + (size_t)s*T*B*4*H, 4*H, 0, 0);
        cudaEventRecord(evD[s], s2);
    }
    for (int s = 0; s < NS-1; s++) {
        k_gemm2<<<dim3(16, 8), 256, 0, s2>>>(XembE + (size_t)s*TBH, enc_Wih, H,
                                             enc_bias, G0E + (size_t)s*T*B*4*H, 4*H, 0, 0);
        cudaEventRecord(evE[s], s2);
    }

    for (int s = 0; s < NS; s++) {
        if (s > 0) {
            cudaStreamWaitEvent(0, evD[s], 0);
            k_dec<<<NBLK, 256, SMEM_DEC>>>(G0D + (size_t)s*T*B*4*H, dec_bias + 4*H,
                                           P_DL0C, P_DL0H, P_DL1X, P_DL1H,
                                           CtxT, DH0T, DH1T, DC0, DC1,
                                           QT, att_W, att_v, Kpre, Eout,
                                           maskp + (s-1)*B*T,
                                           Dout + (size_t)s*TBH);
            cudaEventRecord(evA[s], 0);
            cudaStreamWaitEvent(s2, evA[s], 0);
            k_ln<<<T*B, 128, 0, s2>>>(Dout + (size_t)s*TBH, NormB + (size_t)(s-1)*TBH,
                                      dec_ln_g, dec_ln_b);
            k_gemm2<<<dim3((V + 127)/128, 8), 256, 0, s2>>>(NormB + (size_t)(s-1)*TBH,
                                                            fc_W, H, fc_b, out, V, 1, s-1);
        }
        if (s < NS - 1) {
            cudaStreamWaitEvent(0, evE[s], 0);
            k_encm<<<NBLK, 256, SMEM_ENCM>>>(G0E + (size_t)s*T*B*4*H, enc_bias + 4*H,
                                             P_EL0H, P_EL1X, P_EL1H,
                                             EH0T, EH1T, EC0, EC1,
                                             Eraw, H, T*H);
            k_ln<<<T*B, 128>>>(Eraw, Eout, enc_ln_g, enc_ln_b);
            k_gemm2<<<dim3(4, 8), 256>>>(Eout, att_W + H, 2*H, att_b, Kpre, H, 0, 0);
        }
    }
    // join side stream back into the main stream before graph end
    cudaEventRecord(evEnd, s2);
    cudaStreamWaitEvent(0, evEnd, 0);
}